// round 14
// baseline (speedup 1.0000x reference)
#include <cuda_runtime.h>
#include <cuda_fp16.h>
#include <mma.h>
#include <cstdint>

using namespace nvcuda;

#define L_SEQ 3072
#define D_MODEL 512
#define N_TOKENS 3071

// ======================= scratch (allocation-free) =============================
__device__ float g_Q [L_SEQ * D_MODEL];
__device__ float g_K [L_SEQ * D_MODEL];
__device__ float g_V [L_SEQ * D_MODEL];
__device__ float g_A [L_SEQ * D_MODEL];
__device__ float g_XA[L_SEQ * D_MODEL];
__device__ float g_Y [L_SEQ * D_MODEL];
__device__ float g_X2[L_SEQ * D_MODEL];
__device__ int   g_SEG[L_SEQ];

// activation hi/lo fp16 pairs (two ping-pong pairs), 16B-aligned
__device__ uint4 g_AH1[L_SEQ * D_MODEL * 2 / 16];
__device__ uint4 g_AL1[L_SEQ * D_MODEL * 2 / 16];
__device__ uint4 g_AH2[L_SEQ * D_MODEL * 2 / 16];
__device__ uint4 g_AL2[L_SEQ * D_MODEL * 2 / 16];
__device__ uint4 g_WF [6 * D_MODEL * D_MODEL * 2 / 16];   // weights single fp16

// ======================= fused weight -> fp16 (all 6 in one launch) ===========
struct SplitSrc { const float* s[6]; };

__global__ void __launch_bounds__(256)
split6_kernel(SplitSrc S, __half* __restrict__ wBase, int n4)
{
    const int j = blockIdx.y;
    const float* src = S.s[j];
    __half* w = wBase + j * (D_MODEL * D_MODEL);
    int i = blockIdx.x * blockDim.x + threadIdx.x;
    if (i >= n4) return;
    float4 v = ((const float4*)src)[i];
    __half2 a = __halves2half2(__float2half(v.x), __float2half(v.y));
    __half2 b = __halves2half2(__float2half(v.z), __float2half(v.w));
    uint2 u;
    u.x = *(uint32_t*)&a; u.y = *(uint32_t*)&b;
    ((uint2*)w)[i] = u;
}

// ======================= WMMA fp16x2 pipelined GEMM ===========================
// C[M,N] = A[M,512] @ B[N,512]^T + bias ; A pre-split hi/lo fp16, B single fp16.
// Two MMA passes: Ahi*B + Alo*B. fp32 accumulate.
// CTA tile 128x64, K chunks of 64, cp.async double buffer.
// 256 threads = 8 warps, warp tile 32x32 (wm in 0..3, wn in 0..1).
// smem 92 KB -> 2 CTAs/SM = 16 warps/SM for latency hiding.
struct GemmOut { const __half* b; const float* bias; float* cF;
                 __half* cHi; __half* cLo; };
struct GemmOut3 { GemmOut m[3]; };

#define CH    64
#define NCHUNK (512 / CH)            // 8
#define LDSK  72
#define SM_AH 0
#define SM_AL (128 * LDSK)
#define SM_B  (2 * 128 * LDSK)
#define BUF_ELEMS (2 * 128 * LDSK + 64 * LDSK)       // 23040 half
#define GT_SMEM (2 * BUF_ELEMS * 2)                   // 92160 B

__device__ __forceinline__ uint32_t smem_u32(const void* p) {
    uint32_t a;
    asm("{ .reg .u64 t; cvta.to.shared.u64 t, %1; cvt.u32.u64 %0, t; }" : "=r"(a) : "l"(p));
    return a;
}
__device__ __forceinline__ void cp16(uint32_t sdst, const void* gsrc) {
    asm volatile("cp.async.cg.shared.global [%0], [%1], 16;" :: "r"(sdst), "l"(gsrc));
}

__global__ void __launch_bounds__(256, 2)
gemm_wmma(const __half* __restrict__ Ahi, const __half* __restrict__ Alo,
          GemmOut3 P, int act)
{
    extern __shared__ __align__(128) __half smem[];
    const GemmOut g = P.m[blockIdx.z];
    const uint32_t sb = smem_u32(smem);
    const int tid  = threadIdx.x;
    const int wid  = tid >> 5;     // 0..7
    const int lane = tid & 31;
    const int wm   = wid & 3;      // M-warp 0..3
    const int wn   = wid >> 2;     // N-warp 0..1
    const int rowM0 = blockIdx.y * 128;
    const int colN0 = blockIdx.x * 64;

    const __half* gAh = Ahi + rowM0 * 512;
    const __half* gAl = Alo + rowM0 * 512;
    const __half* gB  = g.b + colN0 * 512;

#define ISSUE(cc, buf) do {                                                          \
        const int koff = (cc) * CH;                                                  \
        const uint32_t bb = sb + (uint32_t)(buf) * (BUF_ELEMS * 2);                  \
        _Pragma("unroll")                                                            \
        for (int i = 0; i < 4; ++i) {                                                \
            int id = tid + i * 256;            /* 0..1023 */                         \
            int r = id >> 3, c8 = (id & 7) * 8;                                      \
            cp16(bb + (SM_AH + r * LDSK + c8) * 2, gAh + r * 512 + koff + c8);       \
            cp16(bb + (SM_AL + r * LDSK + c8) * 2, gAl + r * 512 + koff + c8);       \
        }                                                                            \
        _Pragma("unroll")                                                            \
        for (int i = 0; i < 2; ++i) {                                                \
            int id = tid + i * 256;            /* 0..511 */                          \
            int r = id >> 3, c8 = (id & 7) * 8;                                      \
            cp16(bb + (SM_B + r * LDSK + c8) * 2, gB + r * 512 + koff + c8);         \
        }                                                                            \
        asm volatile("cp.async.commit_group;");                                      \
    } while (0)

    wmma::fragment<wmma::accumulator, 16, 16, 16, float> acc[2][2];
#pragma unroll
    for (int mt = 0; mt < 2; ++mt)
#pragma unroll
        for (int nt = 0; nt < 2; ++nt)
            wmma::fill_fragment(acc[mt][nt], 0.0f);

    ISSUE(0, 0);

    for (int c = 0; c < NCHUNK; ++c) {
        if (c < NCHUNK - 1) {
            ISSUE(c + 1, (c + 1) & 1);
            asm volatile("cp.async.wait_group 1;");
        } else {
            asm volatile("cp.async.wait_group 0;");
        }
        __syncthreads();

        const __half* sAh = smem + (c & 1) * BUF_ELEMS + SM_AH;
        const __half* sAl = smem + (c & 1) * BUF_ELEMS + SM_AL;
        const __half* sB  = smem + (c & 1) * BUF_ELEMS + SM_B;

#pragma unroll
        for (int k16 = 0; k16 < CH / 16; ++k16) {
            wmma::fragment<wmma::matrix_a, 16, 16, 16, __half, wmma::row_major> ah[2], al[2];
            wmma::fragment<wmma::matrix_b, 16, 16, 16, __half, wmma::col_major> bf[2];
#pragma unroll
            for (int mt = 0; mt < 2; ++mt) {
                const int arow = wm * 32 + mt * 16;
                wmma::load_matrix_sync(ah[mt], sAh + arow * LDSK + k16 * 16, LDSK);
                wmma::load_matrix_sync(al[mt], sAl + arow * LDSK + k16 * 16, LDSK);
            }
#pragma unroll
            for (int nt = 0; nt < 2; ++nt)
                wmma::load_matrix_sync(bf[nt], sB + (wn * 32 + nt * 16) * LDSK + k16 * 16, LDSK);
#pragma unroll
            for (int mt = 0; mt < 2; ++mt)
#pragma unroll
                for (int nt = 0; nt < 2; ++nt) {
                    wmma::mma_sync(acc[mt][nt], ah[mt], bf[nt], acc[mt][nt]);
                    wmma::mma_sync(acc[mt][nt], al[mt], bf[nt], acc[mt][nt]);
                }
        }
        __syncthreads();
    }
#undef ISSUE

    // ---------------- epilogue: warp stages 32x32 f32 in smem -----------------
    float* warpArea = (float*)smem + wid * (32 * 32);
#pragma unroll
    for (int mt = 0; mt < 2; ++mt)
#pragma unroll
        for (int nt = 0; nt < 2; ++nt)
            wmma::store_matrix_sync(warpArea + mt * 16 * 32 + nt * 16,
                                    acc[mt][nt], 32, wmma::mem_row_major);
    __syncwarp();

    const int grow = rowM0 + wm * 32 + lane;
    const int gcol = colN0 + wn * 32;
    const float* bi = g.bias + gcol;
    const float* srow = warpArea + lane * 32;
#pragma unroll
    for (int j = 0; j < 8; ++j) {
        float4 v  = *(const float4*)(srow + j * 4);
        float4 bz = *(const float4*)(bi + j * 4);
        float4 o;
        o.x = v.x + bz.x; o.y = v.y + bz.y; o.z = v.z + bz.z; o.w = v.w + bz.w;
        if (act) {
            o.x = o.x > 0.f ? o.x : 0.01f * o.x;
            o.y = o.y > 0.f ? o.y : 0.01f * o.y;
            o.z = o.z > 0.f ? o.z : 0.01f * o.z;
            o.w = o.w > 0.f ? o.w : 0.01f * o.w;
        }
        if (g.cF) *(float4*)(g.cF + grow * 512 + gcol + j * 4) = o;
        if (g.cHi) {
            __half h0 = __float2half(o.x), h1 = __float2half(o.y);
            __half h2 = __float2half(o.z), h3 = __float2half(o.w);
            __half l0 = __float2half(o.x - __half2float(h0));
            __half l1 = __float2half(o.y - __half2float(h1));
            __half l2 = __float2half(o.z - __half2float(h2));
            __half l3 = __float2half(o.w - __half2float(h3));
            __half2 hA = __halves2half2(h0, h1), hB = __halves2half2(h2, h3);
            __half2 lA = __halves2half2(l0, l1), lB = __halves2half2(l2, l3);
            uint2 uh, ul;
            uh.x = *(uint32_t*)&hA; uh.y = *(uint32_t*)&hB;
            ul.x = *(uint32_t*)&lA; ul.y = *(uint32_t*)&lB;
            *(uint2*)(g.cHi + grow * 512 + gcol + j * 4) = uh;
            *(uint2*)(g.cLo + grow * 512 + gcol + j * 4) = ul;
        }
    }
}

// ======================= embedding (emits fp16 hi/lo directly) ================
__global__ void embed_kernel(const int* __restrict__ idx,
                             const float* __restrict__ Wt, const float* __restrict__ bt,
                             const float* __restrict__ Wa, const float* __restrict__ ba,
                             const float* __restrict__ Wm, const float* __restrict__ bm,
                             const float* __restrict__ sos,
                             __half* __restrict__ XH, __half* __restrict__ XL)
{
    int n = blockIdx.x;
    int d = threadIdx.x;             // 512 threads
    float r;
    if (n == 0) {
        r = sos[d];
    } else {
        int id = idx[n - 1];
        int t  = id / 219;           // N_ARGS*N_MAPS = 73*3
        int a  = (id / 3) % 73;
        int m  = id % 3;
        r = bt[d] + ba[d] + bm[d];
        r += Wt[d * 15 + t];
        r += Wa[d * 73 + a];
        r += Wm[d * 3  + m];
    }
    __half h = __float2half(r);
    __half l = __float2half(r - __half2float(h));
    XH[n * D_MODEL + d] = h;
    XL[n * D_MODEL + d] = l;
}

// ======================= segment-start parallel max-scan ======================
__global__ void __launch_bounds__(1024)
seg_kernel(const int* __restrict__ seq_masks, int* __restrict__ seg)
{
    __shared__ int bnd[L_SEQ];
    __shared__ int tmax[1024];
    const int t = threadIdx.x;
    int run = 0;
#pragma unroll
    for (int e = 0; e < 3; ++e) {
        int i = t * 3 + e;
        int v;
        if (i == 0)      v = 0;
        else if (i == 1) v = 1;
        else             v = (seq_masks[i - 1] == 0) ? i : 0;
        run = max(run, v);
        bnd[i] = run;
    }
    tmax[t] = run;
    __syncthreads();
    for (int o = 1; o < 1024; o <<= 1) {
        int u = (t >= o) ? tmax[t - o] : 0;
        __syncthreads();
        tmax[t] = max(tmax[t], u);
        __syncthreads();
    }
    int excl = (t == 0) ? 0 : tmax[t - 1];
#pragma unroll
    for (int e = 0; e < 3; ++e) {
        int i = t * 3 + e;
        seg[i] = max(bnd[i], excl);
    }
}

// ======================= segment-sparse attention (float4, emits fp16 hi/lo) ==
// 128 threads: warp w holds heads 2w, 2w+1; 16 lanes x float4 per head.
__global__ void __launch_bounds__(128)
attn_kernel(const float* __restrict__ Q, const float* __restrict__ K,
            const float* __restrict__ V, const int* __restrict__ seg,
            __half* __restrict__ OH, __half* __restrict__ OL)
{
    const int i    = blockIdx.x;
    const int w    = threadIdx.x >> 5;
    const int lane = threadIdx.x & 31;
    const int h    = (w << 1) + (lane >> 4);   // head 0..7
    const int sl   = lane & 15;
    const int base = (h << 6) + (sl << 2);     // h*64 + sl*4

    float4 q = *(const float4*)(Q + i * D_MODEL + base);
    q.x *= 0.125f; q.y *= 0.125f; q.z *= 0.125f; q.w *= 0.125f;

    float m = -1e30f, l = 0.f;
    float a0 = 0.f, a1 = 0.f, a2 = 0.f, a3 = 0.f;
    const int s = seg[i];

    int j = 0;
    bool first = true;
    for (;;) {
        float4 kv = *(const float4*)(K + j * D_MODEL + base);
        float p = q.x * kv.x + q.y * kv.y + q.z * kv.z + q.w * kv.w;
#pragma unroll
        for (int o = 8; o; o >>= 1) p += __shfl_xor_sync(0xffffffffu, p, o);
        float mnew = fmaxf(m, p);
        float corr = __expf(m - mnew);
        float pe   = __expf(p - mnew);
        float4 vv = *(const float4*)(V + j * D_MODEL + base);
        l  = l  * corr + pe;
        a0 = a0 * corr + pe * vv.x;
        a1 = a1 * corr + pe * vv.y;
        a2 = a2 * corr + pe * vv.z;
        a3 = a3 * corr + pe * vv.w;
        m = mnew;
        if (first) { first = false; j = s; } else { j++; }
        if (j >= i) break;
    }

    float inv = 1.f / l;
    float o0 = a0 * inv, o1 = a1 * inv, o2 = a2 * inv, o3 = a3 * inv;
    __half h0 = __float2half(o0), h1 = __float2half(o1);
    __half h2 = __float2half(o2), h3 = __float2half(o3);
    __half l0 = __float2half(o0 - __half2float(h0));
    __half l1 = __float2half(o1 - __half2float(h1));
    __half l2 = __float2half(o2 - __half2float(h2));
    __half l3 = __float2half(o3 - __half2float(h3));
    __half2 hA = __halves2half2(h0, h1), hB = __halves2half2(h2, h3);
    __half2 lA = __halves2half2(l0, l1), lB = __halves2half2(l2, l3);
    uint2 uh, ul;
    uh.x = *(uint32_t*)&hA; uh.y = *(uint32_t*)&hB;
    ul.x = *(uint32_t*)&lA; ul.y = *(uint32_t*)&lB;
    *(uint2*)(OH + i * D_MODEL + base) = uh;
    *(uint2*)(OL + i * D_MODEL + base) = ul;
}

// ======================= LayerNorm (residual opt; f32 + fp16 hi/lo outs) ======
__global__ void __launch_bounds__(256)
ln_kernel(const float* __restrict__ X, const float* __restrict__ R,
          const float* __restrict__ g, const float* __restrict__ b,
          float* __restrict__ OutF,
          __half* __restrict__ OutH, __half* __restrict__ OutL)
{
    const int row = blockIdx.x;
    const int t   = threadIdx.x;
    float2 v = *(const float2*)(X + row * D_MODEL + (t << 1));
    if (R) {
        float2 r = *(const float2*)(R + row * D_MODEL + (t << 1));
        v.x += r.x; v.y += r.y;
    }
    float s  = v.x + v.y;
    float sq = v.x * v.x + v.y * v.y;
#pragma unroll
    for (int o = 16; o; o >>= 1) {
        s  += __shfl_xor_sync(0xffffffffu, s,  o);
        sq += __shfl_xor_sync(0xffffffffu, sq, o);
    }
    __shared__ float ss[8], sqs[8];
    const int warp = t >> 5, lane = t & 31;
    if (lane == 0) { ss[warp] = s; sqs[warp] = sq; }
    __syncthreads();
    if (warp == 0) {
        float a = (lane < 8) ? ss[lane]  : 0.f;
        float c = (lane < 8) ? sqs[lane] : 0.f;
#pragma unroll
        for (int o = 4; o; o >>= 1) {
            a += __shfl_xor_sync(0xffffffffu, a, o);
            c += __shfl_xor_sync(0xffffffffu, c, o);
        }
        if (lane == 0) { ss[0] = a; sqs[0] = c; }
    }
    __syncthreads();
    const float mu  = ss[0]  * (1.f / 512.f);
    const float var = sqs[0] * (1.f / 512.f) - mu * mu;
    const float inv = rsqrtf(var + 1e-5f);
    float2 gg = *(const float2*)(g + (t << 1));
    float2 bb = *(const float2*)(b + (t << 1));
    float ox = (v.x - mu) * inv * gg.x + bb.x;
    float oy = (v.y - mu) * inv * gg.y + bb.y;
    if (OutF) {
        float2 o; o.x = ox; o.y = oy;
        *(float2*)(OutF + row * D_MODEL + (t << 1)) = o;
    }
    if (OutH) {
        __half h0 = __float2half(ox), h1 = __float2half(oy);
        __half l0 = __float2half(ox - __half2float(h0));
        __half l1 = __float2half(oy - __half2float(h1));
        __half2 hv = __halves2half2(h0, h1), lv = __halves2half2(l0, l1);
        *(__half2*)(OutH + row * D_MODEL + (t << 1)) = hv;
        *(__half2*)(OutL + row * D_MODEL + (t << 1)) = lv;
    }
}

// ======================= host orchestration ===================================
#define W_ELEMS (D_MODEL * D_MODEL)
#define W_N4    (W_ELEMS / 4)

extern "C" void kernel_launch(void* const* d_in, const int* in_sizes, int n_in,
                              void* d_out, int out_size)
{
    const int*   idx  = (const int*)  d_in[0];
    const int*   seqm = (const int*)  d_in[1];
    const float* Wt   = (const float*)d_in[2];
    const float* bt   = (const float*)d_in[3];
    const float* Wa   = (const float*)d_in[4];
    const float* ba   = (const float*)d_in[5];
    const float* Wm   = (const float*)d_in[6];
    const float* bm   = (const float*)d_in[7];
    const float* sos  = (const float*)d_in[8];
    const float* Wq   = (const float*)d_in[9];
    const float* bq   = (const float*)d_in[10];
    const float* Wk   = (const float*)d_in[11];
    const float* bk   = (const float*)d_in[12];
    const float* Wv   = (const float*)d_in[13];
    const float* bv   = (const float*)d_in[14];
    const float* Wo   = (const float*)d_in[15];
    const float* bo   = (const float*)d_in[16];
    const float* W1   = (const float*)d_in[17];
    const float* b1   = (const float*)d_in[18];
    const float* W2   = (const float*)d_in[19];
    const float* b2   = (const float*)d_in[20];
    const float* g1   = (const float*)d_in[21];
    const float* be1  = (const float*)d_in[22];
    const float* g2   = (const float*)d_in[23];
    const float* be2  = (const float*)d_in[24];
    float* out = (float*)d_out;

    float *pQ, *pK, *pV, *pA, *pXA, *pY, *pX2;
    int* pSeg;
    __half *pAH1, *pAL1, *pAH2, *pAL2, *pWF;
    cudaGetSymbolAddress((void**)&pQ,  g_Q);
    cudaGetSymbolAddress((void**)&pK,  g_K);
    cudaGetSymbolAddress((void**)&pV,  g_V);
    cudaGetSymbolAddress((void**)&pA,  g_A);
    cudaGetSymbolAddress((void**)&pXA, g_XA);
    cudaGetSymbolAddress((void**)&pY,  g_Y);
    cudaGetSymbolAddress((void**)&pX2, g_X2);
    cudaGetSymbolAddress((void**)&pSeg, g_SEG);
    cudaGetSymbolAddress((void**)&pAH1, g_AH1);
    cudaGetSymbolAddress((void**)&pAL1, g_AL1);
    cudaGetSymbolAddress((void**)&pAH2, g_AH2);
    cudaGetSymbolAddress((void**)&pAL2, g_AL2);
    cudaGetSymbolAddress((void**)&pWF,  g_WF);

    cudaFuncSetAttribute(gemm_wmma, cudaFuncAttributeMaxDynamicSharedMemorySize, GT_SMEM);

    // weight -> fp16: order q,k,v,o,w1,w2 — single fused launch
    {
        SplitSrc S; S.s[0] = Wq; S.s[1] = Wk; S.s[2] = Wv;
        S.s[3] = Wo; S.s[4] = W1; S.s[5] = W2;
        dim3 sg(W_N4 / 256, 6);
        split6_kernel<<<sg, 256>>>(S, pWF, W_N4);
    }

    embed_kernel<<<L_SEQ, D_MODEL>>>(idx, Wt, bt, Wa, ba, Wm, bm, sos, pAH1, pAL1);
    seg_kernel<<<1, 1024>>>(seqm, pSeg);

    const __half* wf[6];
    for (int j = 0; j < 6; ++j) wf[j] = pWF + j * W_ELEMS;

    dim3 grid1(8, 24, 1), grid3(8, 24, 3);

    for (int layer = 0; layer < 2; ++layer) {
        // QKV: pair1 -> f32 Q,K,V
        {
            GemmOut3 P;
            P.m[0] = {wf[0], bq, pQ, nullptr, nullptr};
            P.m[1] = {wf[1], bk, pK, nullptr, nullptr};
            P.m[2] = {wf[2], bv, pV, nullptr, nullptr};
            gemm_wmma<<<grid3, 256, GT_SMEM>>>(pAH1, pAL1, P, 0);
        }
        // attention -> pair2 hi/lo
        attn_kernel<<<L_SEQ, 128>>>(pQ, pK, pV, pSeg, pAH2, pAL2);
        // Wo: pair2 -> f32 A
        {
            GemmOut3 P; P.m[0] = {wf[3], bo, pA, nullptr, nullptr};
            P.m[1] = P.m[0]; P.m[2] = P.m[0];
            gemm_wmma<<<grid1, 256, GT_SMEM>>>(pAH2, pAL2, P, 0);
        }
        // ln1: A -> f32 XA + pair1 hi/lo
        ln_kernel<<<L_SEQ, 256>>>(pA, nullptr, g1, be1, pXA, pAH1, pAL1);
        // FF1 (leaky): pair1 -> pair2 hi/lo (no f32)
        {
            GemmOut3 P; P.m[0] = {wf[4], b1, nullptr, pAH2, pAL2};
            P.m[1] = P.m[0]; P.m[2] = P.m[0];
            gemm_wmma<<<grid1, 256, GT_SMEM>>>(pAH1, pAL1, P, 1);
        }
        // FF2: pair2 -> f32 Y
        {
            GemmOut3 P; P.m[0] = {wf[5], b2, pY, nullptr, nullptr};
            P.m[1] = P.m[0]; P.m[2] = P.m[0];
            gemm_wmma<<<grid1, 256, GT_SMEM>>>(pAH2, pAL2, P, 0);
        }
        // ln2: Y + XA -> f32 (x2 or out) + pair1 hi/lo for next layer QKV
        ln_kernel<<<L_SEQ, 256>>>(pY, pXA, g2, be2,
                                  (layer == 0) ? pX2 : out, pAH1, pAL1);
    }
}

// round 15
// speedup vs baseline: 1.0570x; 1.0570x over previous
#include <cuda_runtime.h>
#include <cuda_fp16.h>
#include <mma.h>
#include <cstdint>

using namespace nvcuda;

#define L_SEQ 3072
#define D_MODEL 512
#define N_TOKENS 3071

// ======================= scratch (allocation-free) =============================
__device__ float g_Q [L_SEQ * D_MODEL];
__device__ float g_K [L_SEQ * D_MODEL];
__device__ float g_V [L_SEQ * D_MODEL];
__device__ float g_A [L_SEQ * D_MODEL];
__device__ float g_XA[L_SEQ * D_MODEL];
__device__ float g_Y [L_SEQ * D_MODEL];
__device__ float g_X2[L_SEQ * D_MODEL];
__device__ int   g_SEG[L_SEQ];

// activation hi/lo fp16 pairs (two ping-pong pairs), 16B-aligned
__device__ uint4 g_AH1[L_SEQ * D_MODEL * 2 / 16];
__device__ uint4 g_AL1[L_SEQ * D_MODEL * 2 / 16];
__device__ uint4 g_AH2[L_SEQ * D_MODEL * 2 / 16];
__device__ uint4 g_AL2[L_SEQ * D_MODEL * 2 / 16];
__device__ uint4 g_WF [6 * D_MODEL * D_MODEL * 2 / 16];   // weights single fp16

// ======================= fused weight -> fp16 (all 6 in one launch) ===========
struct SplitSrc { const float* s[6]; };

__global__ void __launch_bounds__(256)
split6_kernel(SplitSrc S, __half* __restrict__ wBase, int n4)
{
    const int j = blockIdx.y;
    const float* src = S.s[j];
    __half* w = wBase + j * (D_MODEL * D_MODEL);
    int i = blockIdx.x * blockDim.x + threadIdx.x;
    if (i >= n4) return;
    float4 v = ((const float4*)src)[i];
    __half2 a = __halves2half2(__float2half(v.x), __float2half(v.y));
    __half2 b = __halves2half2(__float2half(v.z), __float2half(v.w));
    uint2 u;
    u.x = *(uint32_t*)&a; u.y = *(uint32_t*)&b;
    ((uint2*)w)[i] = u;
}

// ======================= WMMA fp16x2 pipelined GEMM ===========================
// C[M,N] = A[M,512] @ B[N,512]^T + bias ; A pre-split hi/lo fp16, B single fp16.
// Two MMA passes: Ahi*B + Alo*B. fp32 accumulate.
// CTA tile 128x128 (high A-reuse: total cp.async traffic x0.59 vs 128x64),
// K chunks of 64, cp.async double buffer, 256 threads = 8 warps,
// warp tile 32x64 (wm 0..3, wn 0..1, 2x4 fragments), B frags JIT (reg cap 128).
struct GemmOut { const __half* b; const float* bias; float* cF;
                 __half* cHi; __half* cLo; };
struct GemmOut3 { GemmOut m[3]; };

#define CH    64
#define NCHUNK (512 / CH)            // 8
#define LDSK  72
#define SM_AH 0
#define SM_AL (128 * LDSK)
#define SM_B  (2 * 128 * LDSK)
#define BUF_ELEMS (3 * 128 * LDSK)                   // 27648 half
#define GT_SMEM (2 * BUF_ELEMS * 2)                   // 110592 B

__device__ __forceinline__ uint32_t smem_u32(const void* p) {
    uint32_t a;
    asm("{ .reg .u64 t; cvta.to.shared.u64 t, %1; cvt.u32.u64 %0, t; }" : "=r"(a) : "l"(p));
    return a;
}
__device__ __forceinline__ void cp16(uint32_t sdst, const void* gsrc) {
    asm volatile("cp.async.cg.shared.global [%0], [%1], 16;" :: "r"(sdst), "l"(gsrc));
}

__global__ void __launch_bounds__(256, 2)
gemm_wmma(const __half* __restrict__ Ahi, const __half* __restrict__ Alo,
          GemmOut3 P, int act)
{
    extern __shared__ __align__(128) __half smem[];
    const GemmOut g = P.m[blockIdx.z];
    const uint32_t sb = smem_u32(smem);
    const int tid  = threadIdx.x;
    const int wid  = tid >> 5;     // 0..7
    const int lane = tid & 31;
    const int wm   = wid & 3;      // M-warp 0..3 (32 rows each)
    const int wn   = wid >> 2;     // N-warp 0..1 (64 cols each)
    const int rowM0 = blockIdx.y * 128;
    const int colN0 = blockIdx.x * 128;

    const __half* gAh = Ahi + rowM0 * 512;
    const __half* gAl = Alo + rowM0 * 512;
    const __half* gB  = g.b + colN0 * 512;

    // per chunk: A hi 128x64 = 1024 16B-chunks, A lo 1024, B 128x64 = 1024
    // 256 threads -> 4 each per tile = 12 cp16/thread/chunk
#define ISSUE(cc, buf) do {                                                          \
        const int koff = (cc) * CH;                                                  \
        const uint32_t bb = sb + (uint32_t)(buf) * (BUF_ELEMS * 2);                  \
        _Pragma("unroll")                                                            \
        for (int i = 0; i < 4; ++i) {                                                \
            int id = tid + i * 256;            /* 0..1023 */                         \
            int r = id >> 3, c8 = (id & 7) * 8;                                      \
            cp16(bb + (SM_AH + r * LDSK + c8) * 2, gAh + r * 512 + koff + c8);       \
            cp16(bb + (SM_AL + r * LDSK + c8) * 2, gAl + r * 512 + koff + c8);       \
            cp16(bb + (SM_B  + r * LDSK + c8) * 2, gB  + r * 512 + koff + c8);       \
        }                                                                            \
        asm volatile("cp.async.commit_group;");                                      \
    } while (0)

    wmma::fragment<wmma::accumulator, 16, 16, 16, float> acc[2][4];
#pragma unroll
    for (int mt = 0; mt < 2; ++mt)
#pragma unroll
        for (int nt = 0; nt < 4; ++nt)
            wmma::fill_fragment(acc[mt][nt], 0.0f);

    ISSUE(0, 0);

    for (int c = 0; c < NCHUNK; ++c) {
        if (c < NCHUNK - 1) {
            ISSUE(c + 1, (c + 1) & 1);
            asm volatile("cp.async.wait_group 1;");
        } else {
            asm volatile("cp.async.wait_group 0;");
        }
        __syncthreads();

        const __half* sAh = smem + (c & 1) * BUF_ELEMS + SM_AH;
        const __half* sAl = smem + (c & 1) * BUF_ELEMS + SM_AL;
        const __half* sB  = smem + (c & 1) * BUF_ELEMS + SM_B;

#pragma unroll
        for (int k16 = 0; k16 < CH / 16; ++k16) {
            wmma::fragment<wmma::matrix_a, 16, 16, 16, __half, wmma::row_major> ah[2], al[2];
#pragma unroll
            for (int mt = 0; mt < 2; ++mt) {
                const int arow = wm * 32 + mt * 16;
                wmma::load_matrix_sync(ah[mt], sAh + arow * LDSK + k16 * 16, LDSK);
                wmma::load_matrix_sync(al[mt], sAl + arow * LDSK + k16 * 16, LDSK);
            }
#pragma unroll
            for (int nt = 0; nt < 4; ++nt) {
                wmma::fragment<wmma::matrix_b, 16, 16, 16, __half, wmma::col_major> bf;
                const int bcol = wn * 64 + nt * 16;
                wmma::load_matrix_sync(bf, sB + bcol * LDSK + k16 * 16, LDSK);
#pragma unroll
                for (int mt = 0; mt < 2; ++mt) {
                    wmma::mma_sync(acc[mt][nt], ah[mt], bf, acc[mt][nt]);
                    wmma::mma_sync(acc[mt][nt], al[mt], bf, acc[mt][nt]);
                }
            }
        }
        __syncthreads();
    }
#undef ISSUE

    // ---------------- epilogue: warp stages 32x64 f32 in smem -----------------
    float* warpArea = (float*)smem + wid * (32 * 64);
#pragma unroll
    for (int mt = 0; mt < 2; ++mt)
#pragma unroll
        for (int nt = 0; nt < 4; ++nt)
            wmma::store_matrix_sync(warpArea + mt * 16 * 64 + nt * 16,
                                    acc[mt][nt], 64, wmma::mem_row_major);
    __syncwarp();

    const int grow = rowM0 + wm * 32 + lane;
    const int gcol = colN0 + wn * 64;
    const float* bi = g.bias + gcol;
    const float* srow = warpArea + lane * 64;
#pragma unroll
    for (int j = 0; j < 16; ++j) {
        float4 v  = *(const float4*)(srow + j * 4);
        float4 bz = *(const float4*)(bi + j * 4);
        float4 o;
        o.x = v.x + bz.x; o.y = v.y + bz.y; o.z = v.z + bz.z; o.w = v.w + bz.w;
        if (act) {
            o.x = o.x > 0.f ? o.x : 0.01f * o.x;
            o.y = o.y > 0.f ? o.y : 0.01f * o.y;
            o.z = o.z > 0.f ? o.z : 0.01f * o.z;
            o.w = o.w > 0.f ? o.w : 0.01f * o.w;
        }
        if (g.cF) *(float4*)(g.cF + grow * 512 + gcol + j * 4) = o;
        if (g.cHi) {
            __half h0 = __float2half(o.x), h1 = __float2half(o.y);
            __half h2 = __float2half(o.z), h3 = __float2half(o.w);
            __half l0 = __float2half(o.x - __half2float(h0));
            __half l1 = __float2half(o.y - __half2float(h1));
            __half l2 = __float2half(o.z - __half2float(h2));
            __half l3 = __float2half(o.w - __half2float(h3));
            __half2 hA = __halves2half2(h0, h1), hB = __halves2half2(h2, h3);
            __half2 lA = __halves2half2(l0, l1), lB = __halves2half2(l2, l3);
            uint2 uh, ul;
            uh.x = *(uint32_t*)&hA; uh.y = *(uint32_t*)&hB;
            ul.x = *(uint32_t*)&lA; ul.y = *(uint32_t*)&lB;
            *(uint2*)(g.cHi + grow * 512 + gcol + j * 4) = uh;
            *(uint2*)(g.cLo + grow * 512 + gcol + j * 4) = ul;
        }
    }
}

// ======================= embedding (emits fp16 hi/lo directly) ================
__global__ void embed_kernel(const int* __restrict__ idx,
                             const float* __restrict__ Wt, const float* __restrict__ bt,
                             const float* __restrict__ Wa, const float* __restrict__ ba,
                             const float* __restrict__ Wm, const float* __restrict__ bm,
                             const float* __restrict__ sos,
                             __half* __restrict__ XH, __half* __restrict__ XL)
{
    int n = blockIdx.x;
    int d = threadIdx.x;             // 512 threads
    float r;
    if (n == 0) {
        r = sos[d];
    } else {
        int id = idx[n - 1];
        int t  = id / 219;           // N_ARGS*N_MAPS = 73*3
        int a  = (id / 3) % 73;
        int m  = id % 3;
        r = bt[d] + ba[d] + bm[d];
        r += Wt[d * 15 + t];
        r += Wa[d * 73 + a];
        r += Wm[d * 3  + m];
    }
    __half h = __float2half(r);
    __half l = __float2half(r - __half2float(h));
    XH[n * D_MODEL + d] = h;
    XL[n * D_MODEL + d] = l;
}

// ======================= segment-start parallel max-scan ======================
__global__ void __launch_bounds__(1024)
seg_kernel(const int* __restrict__ seq_masks, int* __restrict__ seg)
{
    __shared__ int bnd[L_SEQ];
    __shared__ int tmax[1024];
    const int t = threadIdx.x;
    int run = 0;
#pragma unroll
    for (int e = 0; e < 3; ++e) {
        int i = t * 3 + e;
        int v;
        if (i == 0)      v = 0;
        else if (i == 1) v = 1;
        else             v = (seq_masks[i - 1] == 0) ? i : 0;
        run = max(run, v);
        bnd[i] = run;
    }
    tmax[t] = run;
    __syncthreads();
    for (int o = 1; o < 1024; o <<= 1) {
        int u = (t >= o) ? tmax[t - o] : 0;
        __syncthreads();
        tmax[t] = max(tmax[t], u);
        __syncthreads();
    }
    int excl = (t == 0) ? 0 : tmax[t - 1];
#pragma unroll
    for (int e = 0; e < 3; ++e) {
        int i = t * 3 + e;
        seg[i] = max(bnd[i], excl);
    }
}

// ======================= segment-sparse attention (float4, emits fp16 hi/lo) ==
// 128 threads: warp w holds heads 2w, 2w+1; 16 lanes x float4 per head.
__global__ void __launch_bounds__(128)
attn_kernel(const float* __restrict__ Q, const float* __restrict__ K,
            const float* __restrict__ V, const int* __restrict__ seg,
            __half* __restrict__ OH, __half* __restrict__ OL)
{
    const int i    = blockIdx.x;
    const int w    = threadIdx.x >> 5;
    const int lane = threadIdx.x & 31;
    const int h    = (w << 1) + (lane >> 4);   // head 0..7
    const int sl   = lane & 15;
    const int base = (h << 6) + (sl << 2);     // h*64 + sl*4

    float4 q = *(const float4*)(Q + i * D_MODEL + base);
    q.x *= 0.125f; q.y *= 0.125f; q.z *= 0.125f; q.w *= 0.125f;

    float m = -1e30f, l = 0.f;
    float a0 = 0.f, a1 = 0.f, a2 = 0.f, a3 = 0.f;
    const int s = seg[i];

    int j = 0;
    bool first = true;
    for (;;) {
        float4 kv = *(const float4*)(K + j * D_MODEL + base);
        float p = q.x * kv.x + q.y * kv.y + q.z * kv.z + q.w * kv.w;
#pragma unroll
        for (int o = 8; o; o >>= 1) p += __shfl_xor_sync(0xffffffffu, p, o);
        float mnew = fmaxf(m, p);
        float corr = __expf(m - mnew);
        float pe   = __expf(p - mnew);
        float4 vv = *(const float4*)(V + j * D_MODEL + base);
        l  = l  * corr + pe;
        a0 = a0 * corr + pe * vv.x;
        a1 = a1 * corr + pe * vv.y;
        a2 = a2 * corr + pe * vv.z;
        a3 = a3 * corr + pe * vv.w;
        m = mnew;
        if (first) { first = false; j = s; } else { j++; }
        if (j >= i) break;
    }

    float inv = 1.f / l;
    float o0 = a0 * inv, o1 = a1 * inv, o2 = a2 * inv, o3 = a3 * inv;
    __half h0 = __float2half(o0), h1 = __float2half(o1);
    __half h2 = __float2half(o2), h3 = __float2half(o3);
    __half l0 = __float2half(o0 - __half2float(h0));
    __half l1 = __float2half(o1 - __half2float(h1));
    __half l2 = __float2half(o2 - __half2float(h2));
    __half l3 = __float2half(o3 - __half2float(h3));
    __half2 hA = __halves2half2(h0, h1), hB = __halves2half2(h2, h3);
    __half2 lA = __halves2half2(l0, l1), lB = __halves2half2(l2, l3);
    uint2 uh, ul;
    uh.x = *(uint32_t*)&hA; uh.y = *(uint32_t*)&hB;
    ul.x = *(uint32_t*)&lA; ul.y = *(uint32_t*)&lB;
    *(uint2*)(OH + i * D_MODEL + base) = uh;
    *(uint2*)(OL + i * D_MODEL + base) = ul;
}

// ======================= LayerNorm (residual opt; f32 + fp16 hi/lo outs) ======
__global__ void __launch_bounds__(256)
ln_kernel(const float* __restrict__ X, const float* __restrict__ R,
          const float* __restrict__ g, const float* __restrict__ b,
          float* __restrict__ OutF,
          __half* __restrict__ OutH, __half* __restrict__ OutL)
{
    const int row = blockIdx.x;
    const int t   = threadIdx.x;
    float2 v = *(const float2*)(X + row * D_MODEL + (t << 1));
    if (R) {
        float2 r = *(const float2*)(R + row * D_MODEL + (t << 1));
        v.x += r.x; v.y += r.y;
    }
    float s  = v.x + v.y;
    float sq = v.x * v.x + v.y * v.y;
#pragma unroll
    for (int o = 16; o; o >>= 1) {
        s  += __shfl_xor_sync(0xffffffffu, s,  o);
        sq += __shfl_xor_sync(0xffffffffu, sq, o);
    }
    __shared__ float ss[8], sqs[8];
    const int warp = t >> 5, lane = t & 31;
    if (lane == 0) { ss[warp] = s; sqs[warp] = sq; }
    __syncthreads();
    if (warp == 0) {
        float a = (lane < 8) ? ss[lane]  : 0.f;
        float c = (lane < 8) ? sqs[lane] : 0.f;
#pragma unroll
        for (int o = 4; o; o >>= 1) {
            a += __shfl_xor_sync(0xffffffffu, a, o);
            c += __shfl_xor_sync(0xffffffffu, c, o);
        }
        if (lane == 0) { ss[0] = a; sqs[0] = c; }
    }
    __syncthreads();
    const float mu  = ss[0]  * (1.f / 512.f);
    const float var = sqs[0] * (1.f / 512.f) - mu * mu;
    const float inv = rsqrtf(var + 1e-5f);
    float2 gg = *(const float2*)(g + (t << 1));
    float2 bb = *(const float2*)(b + (t << 1));
    float ox = (v.x - mu) * inv * gg.x + bb.x;
    float oy = (v.y - mu) * inv * gg.y + bb.y;
    if (OutF) {
        float2 o; o.x = ox; o.y = oy;
        *(float2*)(OutF + row * D_MODEL + (t << 1)) = o;
    }
    if (OutH) {
        __half h0 = __float2half(ox), h1 = __float2half(oy);
        __half l0 = __float2half(ox - __half2float(h0));
        __half l1 = __float2half(oy - __half2float(h1));
        __half2 hv = __halves2half2(h0, h1), lv = __halves2half2(l0, l1);
        *(__half2*)(OutH + row * D_MODEL + (t << 1)) = hv;
        *(__half2*)(OutL + row * D_MODEL + (t << 1)) = lv;
    }
}

// ======================= host orchestration ===================================
#define W_ELEMS (D_MODEL * D_MODEL)
#define W_N4    (W_ELEMS / 4)

extern "C" void kernel_launch(void* const* d_in, const int* in_sizes, int n_in,
                              void* d_out, int out_size)
{
    const int*   idx  = (const int*)  d_in[0];
    const int*   seqm = (const int*)  d_in[1];
    const float* Wt   = (const float*)d_in[2];
    const float* bt   = (const float*)d_in[3];
    const float* Wa   = (const float*)d_in[4];
    const float* ba   = (const float*)d_in[5];
    const float* Wm   = (const float*)d_in[6];
    const float* bm   = (const float*)d_in[7];
    const float* sos  = (const float*)d_in[8];
    const float* Wq   = (const float*)d_in[9];
    const float* bq   = (const float*)d_in[10];
    const float* Wk   = (const float*)d_in[11];
    const float* bk   = (const float*)d_in[12];
    const float* Wv   = (const float*)d_in[13];
    const float* bv   = (const float*)d_in[14];
    const float* Wo   = (const float*)d_in[15];
    const float* bo   = (const float*)d_in[16];
    const float* W1   = (const float*)d_in[17];
    const float* b1   = (const float*)d_in[18];
    const float* W2   = (const float*)d_in[19];
    const float* b2   = (const float*)d_in[20];
    const float* g1   = (const float*)d_in[21];
    const float* be1  = (const float*)d_in[22];
    const float* g2   = (const float*)d_in[23];
    const float* be2  = (const float*)d_in[24];
    float* out = (float*)d_out;

    float *pQ, *pK, *pV, *pA, *pXA, *pY, *pX2;
    int* pSeg;
    __half *pAH1, *pAL1, *pAH2, *pAL2, *pWF;
    cudaGetSymbolAddress((void**)&pQ,  g_Q);
    cudaGetSymbolAddress((void**)&pK,  g_K);
    cudaGetSymbolAddress((void**)&pV,  g_V);
    cudaGetSymbolAddress((void**)&pA,  g_A);
    cudaGetSymbolAddress((void**)&pXA, g_XA);
    cudaGetSymbolAddress((void**)&pY,  g_Y);
    cudaGetSymbolAddress((void**)&pX2, g_X2);
    cudaGetSymbolAddress((void**)&pSeg, g_SEG);
    cudaGetSymbolAddress((void**)&pAH1, g_AH1);
    cudaGetSymbolAddress((void**)&pAL1, g_AL1);
    cudaGetSymbolAddress((void**)&pAH2, g_AH2);
    cudaGetSymbolAddress((void**)&pAL2, g_AL2);
    cudaGetSymbolAddress((void**)&pWF,  g_WF);

    cudaFuncSetAttribute(gemm_wmma, cudaFuncAttributeMaxDynamicSharedMemorySize, GT_SMEM);

    // weight -> fp16: order q,k,v,o,w1,w2 — single fused launch
    {
        SplitSrc S; S.s[0] = Wq; S.s[1] = Wk; S.s[2] = Wv;
        S.s[3] = Wo; S.s[4] = W1; S.s[5] = W2;
        dim3 sg(W_N4 / 256, 6);
        split6_kernel<<<sg, 256>>>(S, pWF, W_N4);
    }

    embed_kernel<<<L_SEQ, D_MODEL>>>(idx, Wt, bt, Wa, ba, Wm, bm, sos, pAH1, pAL1);
    seg_kernel<<<1, 1024>>>(seqm, pSeg);

    const __half* wf[6];
    for (int j = 0; j < 6; ++j) wf[j] = pWF + j * W_ELEMS;

    dim3 grid1(4, 24, 1), grid3(4, 24, 3);

    for (int layer = 0; layer < 2; ++layer) {
        // QKV: pair1 -> f32 Q,K,V
        {
            GemmOut3 P;
            P.m[0] = {wf[0], bq, pQ, nullptr, nullptr};
            P.m[1] = {wf[1], bk, pK, nullptr, nullptr};
            P.m[2] = {wf[2], bv, pV, nullptr, nullptr};
            gemm_wmma<<<grid3, 256, GT_SMEM>>>(pAH1, pAL1, P, 0);
        }
        // attention -> pair2 hi/lo
        attn_kernel<<<L_SEQ, 128>>>(pQ, pK, pV, pSeg, pAH2, pAL2);
        // Wo: pair2 -> f32 A
        {
            GemmOut3 P; P.m[0] = {wf[3], bo, pA, nullptr, nullptr};
            P.m[1] = P.m[0]; P.m[2] = P.m[0];
            gemm_wmma<<<grid1, 256, GT_SMEM>>>(pAH2, pAL2, P, 0);
        }
        // ln1: A -> f32 XA + pair1 hi/lo
        ln_kernel<<<L_SEQ, 256>>>(pA, nullptr, g1, be1, pXA, pAH1, pAL1);
        // FF1 (leaky): pair1 -> pair2 hi/lo (no f32)
        {
            GemmOut3 P; P.m[0] = {wf[4], b1, nullptr, pAH2, pAL2};
            P.m[1] = P.m[0]; P.m[2] = P.m[0];
            gemm_wmma<<<grid1, 256, GT_SMEM>>>(pAH1, pAL1, P, 1);
        }
        // FF2: pair2 -> f32 Y
        {
            GemmOut3 P; P.m[0] = {wf[5], b2, pY, nullptr, nullptr};
            P.m[1] = P.m[0]; P.m[2] = P.m[0];
            gemm_wmma<<<grid1, 256, GT_SMEM>>>(pAH2, pAL2, P, 0);
        }
        // ln2: Y + XA -> f32 (x2 or out) + pair1 hi/lo for next layer QKV
        ln_kernel<<<L_SEQ, 256>>>(pY, pXA, g2, be2,
                                  (layer == 0) ? pX2 : out, pAH1, pAL1);
    }
}

// round 16
// speedup vs baseline: 1.2018x; 1.1370x over previous
#include <cuda_runtime.h>
#include <cuda_fp16.h>
#include <mma.h>
#include <cstdint>

using namespace nvcuda;

#define L_SEQ 3072
#define D_MODEL 512
#define N_TOKENS 3071

// ======================= scratch (allocation-free) =============================
__device__ float g_Q [L_SEQ * D_MODEL];
__device__ float g_K [L_SEQ * D_MODEL];
__device__ float g_V [L_SEQ * D_MODEL];
__device__ float g_A [L_SEQ * D_MODEL];
__device__ float g_XA[L_SEQ * D_MODEL];
__device__ float g_Y [L_SEQ * D_MODEL];
__device__ float g_X2[L_SEQ * D_MODEL];
__device__ int   g_SEG[L_SEQ];

// fp16 activations (two ping-pong buffers), 16B-aligned
__device__ uint4 g_AH1[L_SEQ * D_MODEL * 2 / 16];
__device__ uint4 g_AH2[L_SEQ * D_MODEL * 2 / 16];
__device__ uint4 g_WF [6 * D_MODEL * D_MODEL * 2 / 16];   // weights fp16

// ======================= fused weight -> fp16 (all 6 in one launch) ===========
struct SplitSrc { const float* s[6]; };

__global__ void __launch_bounds__(256)
split6_kernel(SplitSrc S, __half* __restrict__ wBase, int n4)
{
    const int j = blockIdx.y;
    const float* src = S.s[j];
    __half* w = wBase + j * (D_MODEL * D_MODEL);
    int i = blockIdx.x * blockDim.x + threadIdx.x;
    if (i >= n4) return;
    float4 v = ((const float4*)src)[i];
    __half2 a = __halves2half2(__float2half(v.x), __float2half(v.y));
    __half2 b = __halves2half2(__float2half(v.z), __float2half(v.w));
    uint2 u;
    u.x = *(uint32_t*)&a; u.y = *(uint32_t*)&b;
    ((uint2*)w)[i] = u;
}

// ======================= WMMA fp16 single-pass pipelined GEMM =================
// C[M,N] = A[M,512] @ B[N,512]^T + bias ; A,B fp16, fp32 accumulate.
// CTA tile 128x128, K chunks of 64, cp.async TRIPLE buffer (2 chunks in flight),
// 256 threads = 8 warps, warp tile 32x64 (wm 0..3, wn 0..1), B frags JIT.
struct GemmOut { const __half* b; const float* bias; float* cF; __half* cH; };
struct GemmOut3 { GemmOut m[3]; };

#define CH    64
#define NCHUNK (512 / CH)            // 8
#define LDSK  72
#define SM_A  0
#define SM_B  (128 * LDSK)
#define BUF_ELEMS (2 * 128 * LDSK)                   // 18432 half
#define GT_SMEM (3 * BUF_ELEMS * 2)                   // 110592 B

__device__ __forceinline__ uint32_t smem_u32(const void* p) {
    uint32_t a;
    asm("{ .reg .u64 t; cvta.to.shared.u64 t, %1; cvt.u32.u64 %0, t; }" : "=r"(a) : "l"(p));
    return a;
}
__device__ __forceinline__ void cp16(uint32_t sdst, const void* gsrc) {
    asm volatile("cp.async.cg.shared.global [%0], [%1], 16;" :: "r"(sdst), "l"(gsrc));
}

__global__ void __launch_bounds__(256, 2)
gemm_wmma(const __half* __restrict__ Af, GemmOut3 P, int act)
{
    extern __shared__ __align__(128) __half smem[];
    const GemmOut g = P.m[blockIdx.z];
    const uint32_t sb = smem_u32(smem);
    const int tid  = threadIdx.x;
    const int wid  = tid >> 5;     // 0..7
    const int lane = tid & 31;
    const int wm   = wid & 3;      // M-warp 0..3 (32 rows each)
    const int wn   = wid >> 2;     // N-warp 0..1 (64 cols each)
    const int rowM0 = blockIdx.y * 128;
    const int colN0 = blockIdx.x * 128;

    const __half* gA = Af  + rowM0 * 512;
    const __half* gB = g.b + colN0 * 512;

    // per chunk: A 128x64 = 1024 16B-chunks, B 1024 -> 256 threads x 4 each tile
#define ISSUE(cc, buf) do {                                                          \
        const int koff = (cc) * CH;                                                  \
        const uint32_t bb = sb + (uint32_t)(buf) * (BUF_ELEMS * 2);                  \
        _Pragma("unroll")                                                            \
        for (int i = 0; i < 4; ++i) {                                                \
            int id = tid + i * 256;            /* 0..1023 */                         \
            int r = id >> 3, c8 = (id & 7) * 8;                                      \
            cp16(bb + (SM_A + r * LDSK + c8) * 2, gA + r * 512 + koff + c8);         \
            cp16(bb + (SM_B + r * LDSK + c8) * 2, gB + r * 512 + koff + c8);         \
        }                                                                            \
        asm volatile("cp.async.commit_group;");                                      \
    } while (0)

    wmma::fragment<wmma::accumulator, 16, 16, 16, float> acc[2][4];
#pragma unroll
    for (int mt = 0; mt < 2; ++mt)
#pragma unroll
        for (int nt = 0; nt < 4; ++nt)
            wmma::fill_fragment(acc[mt][nt], 0.0f);

    ISSUE(0, 0);
    ISSUE(1, 1);

    for (int c = 0; c < NCHUNK; ++c) {
        if (c + 2 < NCHUNK) {
            ISSUE(c + 2, (c + 2) % 3);
            asm volatile("cp.async.wait_group 2;");
        } else if (c + 2 == NCHUNK + 0) {      // c == 6
            asm volatile("cp.async.wait_group 1;");
        } else {                                // c == 7
            asm volatile("cp.async.wait_group 0;");
        }
        __syncthreads();

        const __half* sA = smem + (c % 3) * BUF_ELEMS + SM_A;
        const __half* sB = smem + (c % 3) * BUF_ELEMS + SM_B;

#pragma unroll
        for (int k16 = 0; k16 < CH / 16; ++k16) {
            wmma::fragment<wmma::matrix_a, 16, 16, 16, __half, wmma::row_major> af[2];
#pragma unroll
            for (int mt = 0; mt < 2; ++mt) {
                const int arow = wm * 32 + mt * 16;
                wmma::load_matrix_sync(af[mt], sA + arow * LDSK + k16 * 16, LDSK);
            }
#pragma unroll
            for (int nt = 0; nt < 4; ++nt) {
                wmma::fragment<wmma::matrix_b, 16, 16, 16, __half, wmma::col_major> bf;
                const int bcol = wn * 64 + nt * 16;
                wmma::load_matrix_sync(bf, sB + bcol * LDSK + k16 * 16, LDSK);
#pragma unroll
                for (int mt = 0; mt < 2; ++mt)
                    wmma::mma_sync(acc[mt][nt], af[mt], bf, acc[mt][nt]);
            }
        }
        __syncthreads();
    }
#undef ISSUE

    // ---------------- epilogue: warp stages 32x64 f32 in smem -----------------
    float* warpArea = (float*)smem + wid * (32 * 64);
#pragma unroll
    for (int mt = 0; mt < 2; ++mt)
#pragma unroll
        for (int nt = 0; nt < 4; ++nt)
            wmma::store_matrix_sync(warpArea + mt * 16 * 64 + nt * 16,
                                    acc[mt][nt], 64, wmma::mem_row_major);
    __syncwarp();

    const int grow = rowM0 + wm * 32 + lane;
    const int gcol = colN0 + wn * 64;
    const float* bi = g.bias + gcol;
    const float* srow = warpArea + lane * 64;
#pragma unroll
    for (int j = 0; j < 16; ++j) {
        float4 v  = *(const float4*)(srow + j * 4);
        float4 bz = *(const float4*)(bi + j * 4);
        float4 o;
        o.x = v.x + bz.x; o.y = v.y + bz.y; o.z = v.z + bz.z; o.w = v.w + bz.w;
        if (act) {
            o.x = o.x > 0.f ? o.x : 0.01f * o.x;
            o.y = o.y > 0.f ? o.y : 0.01f * o.y;
            o.z = o.z > 0.f ? o.z : 0.01f * o.z;
            o.w = o.w > 0.f ? o.w : 0.01f * o.w;
        }
        if (g.cF) *(float4*)(g.cF + grow * 512 + gcol + j * 4) = o;
        if (g.cH) {
            __half2 hA = __halves2half2(__float2half(o.x), __float2half(o.y));
            __half2 hB = __halves2half2(__float2half(o.z), __float2half(o.w));
            uint2 uh;
            uh.x = *(uint32_t*)&hA; uh.y = *(uint32_t*)&hB;
            *(uint2*)(g.cH + grow * 512 + gcol + j * 4) = uh;
        }
    }
}

// ======================= embedding (emits fp16 directly) ======================
__global__ void embed_kernel(const int* __restrict__ idx,
                             const float* __restrict__ Wt, const float* __restrict__ bt,
                             const float* __restrict__ Wa, const float* __restrict__ ba,
                             const float* __restrict__ Wm, const float* __restrict__ bm,
                             const float* __restrict__ sos,
                             __half* __restrict__ XH)
{
    int n = blockIdx.x;
    int d = threadIdx.x;             // 512 threads
    float r;
    if (n == 0) {
        r = sos[d];
    } else {
        int id = idx[n - 1];
        int t  = id / 219;           // N_ARGS*N_MAPS = 73*3
        int a  = (id / 3) % 73;
        int m  = id % 3;
        r = bt[d] + ba[d] + bm[d];
        r += Wt[d * 15 + t];
        r += Wa[d * 73 + a];
        r += Wm[d * 3  + m];
    }
    XH[n * D_MODEL + d] = __float2half(r);
}

// ======================= segment-start parallel max-scan ======================
__global__ void __launch_bounds__(1024)
seg_kernel(const int* __restrict__ seq_masks, int* __restrict__ seg)
{
    __shared__ int bnd[L_SEQ];
    __shared__ int tmax[1024];
    const int t = threadIdx.x;
    int run = 0;
#pragma unroll
    for (int e = 0; e < 3; ++e) {
        int i = t * 3 + e;
        int v;
        if (i == 0)      v = 0;
        else if (i == 1) v = 1;
        else             v = (seq_masks[i - 1] == 0) ? i : 0;
        run = max(run, v);
        bnd[i] = run;
    }
    tmax[t] = run;
    __syncthreads();
    for (int o = 1; o < 1024; o <<= 1) {
        int u = (t >= o) ? tmax[t - o] : 0;
        __syncthreads();
        tmax[t] = max(tmax[t], u);
        __syncthreads();
    }
    int excl = (t == 0) ? 0 : tmax[t - 1];
#pragma unroll
    for (int e = 0; e < 3; ++e) {
        int i = t * 3 + e;
        seg[i] = max(bnd[i], excl);
    }
}

// ======================= segment-sparse attention (float4, emits fp16) ========
// 128 threads: warp w holds heads 2w, 2w+1; 16 lanes x float4 per head.
__global__ void __launch_bounds__(128)
attn_kernel(const float* __restrict__ Q, const float* __restrict__ K,
            const float* __restrict__ V, const int* __restrict__ seg,
            __half* __restrict__ OH)
{
    const int i    = blockIdx.x;
    const int w    = threadIdx.x >> 5;
    const int lane = threadIdx.x & 31;
    const int h    = (w << 1) + (lane >> 4);   // head 0..7
    const int sl   = lane & 15;
    const int base = (h << 6) + (sl << 2);     // h*64 + sl*4

    float4 q = *(const float4*)(Q + i * D_MODEL + base);
    q.x *= 0.125f; q.y *= 0.125f; q.z *= 0.125f; q.w *= 0.125f;

    float m = -1e30f, l = 0.f;
    float a0 = 0.f, a1 = 0.f, a2 = 0.f, a3 = 0.f;
    const int s = seg[i];

    int j = 0;
    bool first = true;
    for (;;) {
        float4 kv = *(const float4*)(K + j * D_MODEL + base);
        float p = q.x * kv.x + q.y * kv.y + q.z * kv.z + q.w * kv.w;
#pragma unroll
        for (int o = 8; o; o >>= 1) p += __shfl_xor_sync(0xffffffffu, p, o);
        float mnew = fmaxf(m, p);
        float corr = __expf(m - mnew);
        float pe   = __expf(p - mnew);
        float4 vv = *(const float4*)(V + j * D_MODEL + base);
        l  = l  * corr + pe;
        a0 = a0 * corr + pe * vv.x;
        a1 = a1 * corr + pe * vv.y;
        a2 = a2 * corr + pe * vv.z;
        a3 = a3 * corr + pe * vv.w;
        m = mnew;
        if (first) { first = false; j = s; } else { j++; }
        if (j >= i) break;
    }

    float inv = 1.f / l;
    __half2 hA = __halves2half2(__float2half(a0 * inv), __float2half(a1 * inv));
    __half2 hB = __halves2half2(__float2half(a2 * inv), __float2half(a3 * inv));
    uint2 uh;
    uh.x = *(uint32_t*)&hA; uh.y = *(uint32_t*)&hB;
    *(uint2*)(OH + i * D_MODEL + base) = uh;
}

// ======================= LayerNorm (residual opt; f32 + fp16 outs) ============
__global__ void __launch_bounds__(256)
ln_kernel(const float* __restrict__ X, const float* __restrict__ R,
          const float* __restrict__ g, const float* __restrict__ b,
          float* __restrict__ OutF, __half* __restrict__ OutH)
{
    const int row = blockIdx.x;
    const int t   = threadIdx.x;
    float2 v = *(const float2*)(X + row * D_MODEL + (t << 1));
    if (R) {
        float2 r = *(const float2*)(R + row * D_MODEL + (t << 1));
        v.x += r.x; v.y += r.y;
    }
    float s  = v.x + v.y;
    float sq = v.x * v.x + v.y * v.y;
#pragma unroll
    for (int o = 16; o; o >>= 1) {
        s  += __shfl_xor_sync(0xffffffffu, s,  o);
        sq += __shfl_xor_sync(0xffffffffu, sq, o);
    }
    __shared__ float ss[8], sqs[8];
    const int warp = t >> 5, lane = t & 31;
    if (lane == 0) { ss[warp] = s; sqs[warp] = sq; }
    __syncthreads();
    if (warp == 0) {
        float a = (lane < 8) ? ss[lane]  : 0.f;
        float c = (lane < 8) ? sqs[lane] : 0.f;
#pragma unroll
        for (int o = 4; o; o >>= 1) {
            a += __shfl_xor_sync(0xffffffffu, a, o);
            c += __shfl_xor_sync(0xffffffffu, c, o);
        }
        if (lane == 0) { ss[0] = a; sqs[0] = c; }
    }
    __syncthreads();
    const float mu  = ss[0]  * (1.f / 512.f);
    const float var = sqs[0] * (1.f / 512.f) - mu * mu;
    const float inv = rsqrtf(var + 1e-5f);
    float2 gg = *(const float2*)(g + (t << 1));
    float2 bb = *(const float2*)(b + (t << 1));
    float ox = (v.x - mu) * inv * gg.x + bb.x;
    float oy = (v.y - mu) * inv * gg.y + bb.y;
    if (OutF) {
        float2 o; o.x = ox; o.y = oy;
        *(float2*)(OutF + row * D_MODEL + (t << 1)) = o;
    }
    if (OutH) {
        __half2 hv = __halves2half2(__float2half(ox), __float2half(oy));
        *(__half2*)(OutH + row * D_MODEL + (t << 1)) = hv;
    }
}

// ======================= host orchestration ===================================
#define W_ELEMS (D_MODEL * D_MODEL)
#define W_N4    (W_ELEMS / 4)

extern "C" void kernel_launch(void* const* d_in, const int* in_sizes, int n_in,
                              void* d_out, int out_size)
{
    const int*   idx  = (const int*)  d_in[0];
    const int*   seqm = (const int*)  d_in[1];
    const float* Wt   = (const float*)d_in[2];
    const float* bt   = (const float*)d_in[3];
    const float* Wa   = (const float*)d_in[4];
    const float* ba   = (const float*)d_in[5];
    const float* Wm   = (const float*)d_in[6];
    const float* bm   = (const float*)d_in[7];
    const float* sos  = (const float*)d_in[8];
    const float* Wq   = (const float*)d_in[9];
    const float* bq   = (const float*)d_in[10];
    const float* Wk   = (const float*)d_in[11];
    const float* bk   = (const float*)d_in[12];
    const float* Wv   = (const float*)d_in[13];
    const float* bv   = (const float*)d_in[14];
    const float* Wo   = (const float*)d_in[15];
    const float* bo   = (const float*)d_in[16];
    const float* W1   = (const float*)d_in[17];
    const float* b1   = (const float*)d_in[18];
    const float* W2   = (const float*)d_in[19];
    const float* b2   = (const float*)d_in[20];
    const float* g1   = (const float*)d_in[21];
    const float* be1  = (const float*)d_in[22];
    const float* g2   = (const float*)d_in[23];
    const float* be2  = (const float*)d_in[24];
    float* out = (float*)d_out;

    float *pQ, *pK, *pV, *pA, *pXA, *pY, *pX2;
    int* pSeg;
    __half *pAH1, *pAH2, *pWF;
    cudaGetSymbolAddress((void**)&pQ,  g_Q);
    cudaGetSymbolAddress((void**)&pK,  g_K);
    cudaGetSymbolAddress((void**)&pV,  g_V);
    cudaGetSymbolAddress((void**)&pA,  g_A);
    cudaGetSymbolAddress((void**)&pXA, g_XA);
    cudaGetSymbolAddress((void**)&pY,  g_Y);
    cudaGetSymbolAddress((void**)&pX2, g_X2);
    cudaGetSymbolAddress((void**)&pSeg, g_SEG);
    cudaGetSymbolAddress((void**)&pAH1, g_AH1);
    cudaGetSymbolAddress((void**)&pAH2, g_AH2);
    cudaGetSymbolAddress((void**)&pWF,  g_WF);

    cudaFuncSetAttribute(gemm_wmma, cudaFuncAttributeMaxDynamicSharedMemorySize, GT_SMEM);

    // weight -> fp16: order q,k,v,o,w1,w2 — single fused launch
    {
        SplitSrc S; S.s[0] = Wq; S.s[1] = Wk; S.s[2] = Wv;
        S.s[3] = Wo; S.s[4] = W1; S.s[5] = W2;
        dim3 sg(W_N4 / 256, 6);
        split6_kernel<<<sg, 256>>>(S, pWF, W_N4);
    }

    embed_kernel<<<L_SEQ, D_MODEL>>>(idx, Wt, bt, Wa, ba, Wm, bm, sos, pAH1);
    seg_kernel<<<1, 1024>>>(seqm, pSeg);

    const __half* wf[6];
    for (int j = 0; j < 6; ++j) wf[j] = pWF + j * W_ELEMS;

    dim3 grid1(4, 24, 1), grid3(4, 24, 3);

    for (int layer = 0; layer < 2; ++layer) {
        // QKV: AH1 -> f32 Q,K,V
        {
            GemmOut3 P;
            P.m[0] = {wf[0], bq, pQ, nullptr};
            P.m[1] = {wf[1], bk, pK, nullptr};
            P.m[2] = {wf[2], bv, pV, nullptr};
            gemm_wmma<<<grid3, 256, GT_SMEM>>>(pAH1, P, 0);
        }
        // attention -> AH2 fp16
        attn_kernel<<<L_SEQ, 128>>>(pQ, pK, pV, pSeg, pAH2);
        // Wo: AH2 -> f32 A
        {
            GemmOut3 P; P.m[0] = {wf[3], bo, pA, nullptr};
            P.m[1] = P.m[0]; P.m[2] = P.m[0];
            gemm_wmma<<<grid1, 256, GT_SMEM>>>(pAH2, P, 0);
        }
        // ln1: A -> f32 XA + AH1 fp16
        ln_kernel<<<L_SEQ, 256>>>(pA, nullptr, g1, be1, pXA, pAH1);
        // FF1 (leaky): AH1 -> AH2 fp16 (no f32)
        {
            GemmOut3 P; P.m[0] = {wf[4], b1, nullptr, pAH2};
            P.m[1] = P.m[0]; P.m[2] = P.m[0];
            gemm_wmma<<<grid1, 256, GT_SMEM>>>(pAH1, P, 1);
        }
        // FF2: AH2 -> f32 Y
        {
            GemmOut3 P; P.m[0] = {wf[5], b2, pY, nullptr};
            P.m[1] = P.m[0]; P.m[2] = P.m[0];
            gemm_wmma<<<grid1, 256, GT_SMEM>>>(pAH2, P, 0);
        }
        // ln2: Y + XA -> f32 (x2 or out) + AH1 fp16 for next layer QKV
        ln_kernel<<<L_SEQ, 256>>>(pY, pXA, g2, be2,
                                  (layer == 0) ? pX2 : out, pAH1);
    }
}